// round 14
// baseline (speedup 1.0000x reference)
#include <cuda_runtime.h>
#include <cstdint>
#include <math.h>

#define E_N      200000
#define A_NUM    8000
#define T_N      1000000
#define NCAT     672
#define EMB_EDGE 512
#define N_TILES  1563
#define NSL      261
#define L_TILES  6

#define OFF_M    0ull
#define OFF_AT   102400000ull
#define OFF_OUT  105600000ull
#define OFF_RE2E 108800000ull
#define OFF_CIR  112000000ull

#define GEMM_BLKS 504
#define HIST_BLKS 128
#define KB 12
#define TRIP_BLKS 15625           // ceil((T_N/2)*16/512)
#define MIX_GRID  16704           // 1044 m-blocks (every 16th) + trip blocks

__device__ float g_radW1[(size_t)E_N * 112];
__device__ float g_hW[2ull * A_NUM * EMB_EDGE];
__device__ float g_Wcat[128 * NCAT];            // [k][n]
__device__ int   g_cnt[128];
__device__ int   g_pos[128];
__device__ int   g_done;
__device__ int   g_order[N_TILES * 128];

// ---------------- helpers ----------------
__device__ __forceinline__ void ffma2(unsigned long long& d, unsigned long long a,
                                      unsigned long long b) {
    asm("fma.rn.f32x2 %0, %1, %2, %3;" : "=l"(d) : "l"(a), "l"(b), "l"(d));
}
__device__ __forceinline__ unsigned long long pack2(float x, float y) {
    unsigned long long r;
    asm("mov.b64 %0, {%1, %2};" : "=l"(r) : "f"(x), "f"(y));
    return r;
}
union F4U { float4 f; unsigned long long u[2]; };

__device__ __forceinline__ int edge_r0(float d) {
    float u = d * (127.0f / 12.0f);
    int r0 = __float2int_rn(u);
    return max(0, min(127, r0));
}

// ---------------- kernel 0: init + build wcat ----------------
__global__ void k_init(const float* __restrict__ Wt, const float* __restrict__ Wc,
                       const float* __restrict__ Wh, const float* __restrict__ Wo,
                       const float* __restrict__ We) {
    int i = blockIdx.x * blockDim.x + threadIdx.x;
    if (blockIdx.x == 0) {
        int tid = threadIdx.x;
        if (tid < 128) { g_cnt[tid] = 0; g_pos[tid] = 0; }
        if (tid == 128) g_done = 0;
        if (tid >= 129 && tid < 129 + (N_TILES * 128 - E_N))
            g_order[E_N + tid - 129] = -1;
    }
    if (i >= 128 * NCAT) return;
    int k = i / NCAT, n = i - k * NCAT;
    float v;
    if (n < 16)        v = Wt[k * 16 + n];
    else if (n < 32)   v = Wh[k * 16 + (n - 16)];
    else if (n < 48)   v = Wo[k * 16 + (n - 32)];
    else if (n < 160)  v = Wc[k * 112 + (n - 48)];
    else               v = We[(size_t)(512 + k) * EMB_EDGE + (n - 160)];
    g_Wcat[i] = v;
}

// ---------------- kernel 1: gemm_hw + histogram/scan ----------------
__global__ void __launch_bounds__(256, 2)
k_gemm_hist(const float* __restrict__ h, const float* __restrict__ We,
            const float* __restrict__ dist) {
    __shared__ float As[32][132];
    __shared__ float Bs[32][132];

    if (blockIdx.x >= GEMM_BLKS) {
        __shared__ int scnt[128];
        __shared__ int sv[128];
        __shared__ int sdone;
        const int hb = blockIdx.x - GEMM_BLKS;
        const int tid = threadIdx.x;
        if (tid < 128) scnt[tid] = 0;
        __syncthreads();
        for (int e = hb * 256 + tid; e < E_N; e += HIST_BLKS * 256)
            atomicAdd(&scnt[edge_r0(dist[e])], 1);
        __syncthreads();
        if (tid < 128 && scnt[tid] > 0) atomicAdd(&g_cnt[tid], scnt[tid]);
        __threadfence();
        if (tid == 0) {
            int o = atomicAdd(&g_done, 1);
            sdone = (o == HIST_BLKS - 1) ? 1 : 0;
        }
        __syncthreads();
        if (!sdone) return;
        int c0 = 0;
        if (tid < 128) { c0 = *((volatile int*)&g_cnt[tid]); sv[tid] = c0; }
        __syncthreads();
        for (int o = 1; o < 128; o <<= 1) {
            int v = 0;
            if (tid < 128 && tid >= o) v = sv[tid - o];
            __syncthreads();
            if (tid < 128) sv[tid] += v;
            __syncthreads();
        }
        if (tid < 128) g_pos[tid] = sv[tid] - c0;
        return;
    }

    const int bx = blockIdx.x;
    const int z = bx / 252;
    const int rem = bx % 252;
    const int by = rem / 4;
    const int bnx = rem % 4;
    const float* B = We + (size_t)z * 256 * EMB_EDGE;
    float* C = g_hW + (size_t)z * A_NUM * EMB_EDGE;
    const int m0 = by * 128;
    const int n0 = bnx * 128;
    const int tid = threadIdx.x;
    const int tx = tid & 15, ty = tid >> 4;

    unsigned long long acc[8][4];
#pragma unroll
    for (int i = 0; i < 8; ++i)
#pragma unroll
        for (int j = 0; j < 4; ++j) acc[i][j] = 0ull;

    for (int k0 = 0; k0 < 256; k0 += 32) {
        if (k0) __syncthreads();
#pragma unroll
        for (int i = tid; i < 128 * 32; i += 256) {
            int m = i >> 5, kk = i & 31;
            As[kk][m] = (m0 + m < A_NUM) ? h[(size_t)(m0 + m) * 256 + k0 + kk] : 0.f;
        }
#pragma unroll
        for (int i = tid * 4; i < 32 * 128; i += 1024) {
            int kk = i >> 7, n = i & 127;
            *(float4*)&Bs[kk][n] = *(const float4*)&B[(size_t)(k0 + kk) * EMB_EDGE + n0 + n];
        }
        __syncthreads();
#pragma unroll
        for (int kk = 0; kk < 32; ++kk) {
            float4 a0 = *(const float4*)&As[kk][ty * 8];
            float4 a1 = *(const float4*)&As[kk][ty * 8 + 4];
            F4U b0, b1;
            b0.f = *(const float4*)&Bs[kk][tx * 8];
            b1.f = *(const float4*)&Bs[kk][tx * 8 + 4];
            unsigned long long bb[4] = {b0.u[0], b0.u[1], b1.u[0], b1.u[1]};
            float av[8] = {a0.x, a0.y, a0.z, a0.w, a1.x, a1.y, a1.z, a1.w};
#pragma unroll
            for (int i = 0; i < 8; ++i) {
                unsigned long long a2 = pack2(av[i], av[i]);
#pragma unroll
                for (int j = 0; j < 4; ++j) ffma2(acc[i][j], a2, bb[j]);
            }
        }
    }
#pragma unroll
    for (int i = 0; i < 8; ++i) {
        int m = m0 + ty * 8 + i;
        if (m >= A_NUM) continue;
        float v[8];
#pragma unroll
        for (int j = 0; j < 4; ++j) {
            v[2 * j]     = __uint_as_float((unsigned)(acc[i][j] & 0xffffffffull));
            v[2 * j + 1] = __uint_as_float((unsigned)(acc[i][j] >> 32));
        }
        float* dst = C + (size_t)m * EMB_EDGE + n0 + tx * 8;
        *(float4*)dst       = make_float4(v[0], v[1], v[2], v[3]);
        *(float4*)(dst + 4) = make_float4(v[4], v[5], v[6], v[7]);
    }
}

// ---------------- kernel 2: scatter ----------------
__global__ void __launch_bounds__(256)
k_scatter(const float* __restrict__ dist) {
    __shared__ int scnt[128];
    __shared__ int sbase[128];
    const int tid = threadIdx.x;
    const int base = blockIdx.x * 1024;
    if (tid < 128) scnt[tid] = 0;
    __syncthreads();
    int r0[4], lp[4];
#pragma unroll
    for (int j = 0; j < 4; ++j) {
        int e = base + j * 256 + tid;
        r0[j] = -1;
        if (e < E_N) { r0[j] = edge_r0(dist[e]); lp[j] = atomicAdd(&scnt[r0[j]], 1); }
    }
    __syncthreads();
    if (tid < 128 && scnt[tid] > 0) sbase[tid] = atomicAdd(&g_pos[tid], scnt[tid]);
    __syncthreads();
#pragma unroll
    for (int j = 0; j < 4; ++j) {
        int e = base + j * 256 + tid;
        if (e < E_N) g_order[sbase[r0[j]] + lp[j]] = e;
    }
}

// ---------------- banded GEMM tile body (round-12 proven version) ----------
__device__ __forceinline__ void band_run(
    int ci, int slice, bool needsHW,
    const float* __restrict__ dist, const int* __restrict__ eis,
    const int* __restrict__ eit, float* __restrict__ out,
    float (*Bs)[132], float (*myA)[16])
{
    const int n0 = ci * 128;
    const int tid = threadIdx.x;
    const int lane = tid & 31;
    const int warp = tid >> 5;
    const int warpRow = warp >> 1;
    const int warpCol = warp & 1;
    const int rblk = lane >> 3;
    const int cblk = lane & 7;
    const int c0 = warpCol * 64 + cblk * 4;
    const int el = lane & 15;
    const int dir = lane >> 4;
    const int t0 = slice * L_TILES;
    const int t1 = min(t0 + L_TILES, N_TILES);
    const float E1 = 0.36787944117144233f;

    int e0p = t0 * 128;
    int id0N = g_order[e0p];
    int idN  = g_order[e0p + warpRow * 16 + el];
    float dist0N = dist[max(id0N, 0)];
    float distN  = dist[max(idN, 0)];
    int siN = 0, tiN = 0;
    if (needsHW) { int cidx = max(idN, 0); siN = eis[cidx]; tiN = eit[cidx]; }

    int kmin_prev = -1;
    for (int t = t0; t < t1; ++t) {
        const int e0 = t * 128;
        const float dist0 = dist0N, myd = distN;
        const int idp = idN, sip = siN, tip = tiN;
        const int kmin = max(0, edge_r0(dist0) - 5);

        const bool hasNext = (t + 1 < t1);
        if (hasNext) {
            const int e0n = (t + 1) * 128;
            id0N = g_order[e0n];
            idN  = g_order[e0n + warpRow * 16 + el];
        }

        if (kmin != kmin_prev) {
            __syncthreads();
            for (int i = tid; i < KB * 32; i += 512) {
                int k = i >> 5;
                int n = (i & 31) * 4;
                int gk = kmin + k, gn = n0 + n;
                float4 w = make_float4(0.f, 0.f, 0.f, 0.f);
                if (gk < 128 && gn < NCAT)
                    w = *(const float4*)&g_Wcat[gk * NCAT + gn];
                *(float4*)&Bs[k][n] = w;
            }
            __syncthreads();
            kmin_prev = kmin;
        }

        {
            float f = 0.f, vc = 0.f;
            int r0v = kmin;
            if (idp >= 0) {
                float ds = myd * (1.0f / 12.0f);
                float ds2 = ds * ds, ds5 = ds2 * ds2 * ds;
                float env = (ds < 1.f) ? (1.f + ds5 * (-21.f + ds * (35.f - 15.f * ds))) : 0.f;
                float u = ds * 127.f;
                r0v = __float2int_rn(u);
                r0v = max(0, min(127, r0v));
                f = u - (float)r0v;
                vc = env * expf(-0.5f * f * f);
            }
            const int center = min(r0v - kmin, KB - 1);
            if (dir == 0) {
                float v = vc;
                myA[center][el] = v;
                float ratio = __expf(-f - 0.5f);
                for (int rel = center - 1; rel >= 0; --rel) {
                    v *= ratio; ratio *= E1;
                    myA[rel][el] = v;
                }
            } else {
                float ratio = __expf(f - 0.5f);
                float v = vc;
                for (int rel = center + 1; rel < KB; ++rel) {
                    v *= ratio; ratio *= E1;
                    myA[rel][el] = v;
                }
            }
        }
        __syncwarp();

        if (hasNext) {
            dist0N = dist[max(id0N, 0)];
            distN  = dist[max(idN, 0)];
            if (needsHW) { int cidx = max(idN, 0); siN = eis[cidx]; tiN = eit[cidx]; }
        }

        unsigned long long acc[4][4];
#pragma unroll
        for (int i = 0; i < 4; ++i)
#pragma unroll
            for (int j = 0; j < 4; ++j) acc[i][j] = 0ull;
#pragma unroll
        for (int kk = 0; kk < KB; ++kk) {
            float4 a = *(const float4*)&myA[kk][rblk * 4];
            F4U b0, b1;
            b0.f = *(const float4*)&Bs[kk][c0];
            b1.f = *(const float4*)&Bs[kk][c0 + 32];
            unsigned long long bb[4] = {b0.u[0], b0.u[1], b1.u[0], b1.u[1]};
            float av[4] = {a.x, a.y, a.z, a.w};
#pragma unroll
            for (int i = 0; i < 4; ++i) {
                unsigned long long a2 = pack2(av[i], av[i]);
#pragma unroll
                for (int j = 0; j < 4; ++j) ffma2(acc[i][j], a2, bb[j]);
            }
        }
        __syncwarp();

        const int nbase = n0 + c0;
#pragma unroll
        for (int i = 0; i < 4; ++i) {
            const int src = rblk * 4 + i;
            const int id2 = __shfl_sync(0xffffffffu, idp, src, 32);
            const int si  = __shfl_sync(0xffffffffu, sip, src, 32);
            const int ti  = __shfl_sync(0xffffffffu, tip, src, 32);
            if (id2 < 0) continue;
            float v[8];
#pragma unroll
            for (int j = 0; j < 4; ++j) {
                v[2 * j]     = __uint_as_float((unsigned)(acc[i][j] & 0xffffffffull));
                v[2 * j + 1] = __uint_as_float((unsigned)(acc[i][j] >> 32));
            }
#pragma unroll
            for (int q = 0; q < 2; ++q) {
                const int nbq = nbase + q * 32;
                if (nbq >= NCAT) continue;
                const float* vq = v + q * 4;
                if (nbq >= 160) {
                    int j2 = nbq - 160;
                    const float* hw1 = g_hW + (size_t)si * EMB_EDGE + j2;
                    const float* hw2 = g_hW + (size_t)A_NUM * EMB_EDGE
                                       + (size_t)ti * EMB_EDGE + j2;
                    float4 a4 = *(const float4*)hw1;
                    float4 b4 = *(const float4*)hw2;
                    float x0 = vq[0] + a4.x + b4.x;
                    float x1 = vq[1] + a4.y + b4.y;
                    float x2 = vq[2] + a4.z + b4.z;
                    float x3 = vq[3] + a4.w + b4.w;
                    float4 o;
                    o.x = x0 * (1.0f / 0.6f) / (1.0f + __expf(-x0));
                    o.y = x1 * (1.0f / 0.6f) / (1.0f + __expf(-x1));
                    o.z = x2 * (1.0f / 0.6f) / (1.0f + __expf(-x2));
                    o.w = x3 * (1.0f / 0.6f) / (1.0f + __expf(-x3));
                    *(float4*)(out + OFF_M + (size_t)id2 * EMB_EDGE + j2) = o;
                } else if (nbq >= 48) {
                    *(float4*)(g_radW1 + (size_t)id2 * 112 + (nbq - 48)) =
                        make_float4(vq[0], vq[1], vq[2], vq[3]);
                } else {
                    int seg = nbq >> 4;
                    size_t base = (seg == 0) ? OFF_RE2E : (seg == 1) ? OFF_AT : OFF_OUT;
                    *(float4*)(out + base + (size_t)id2 * 16 + (nbq & 15)) =
                        make_float4(vq[0], vq[1], vq[2], vq[3]);
                }
            }
        }
    }
}

// ---------------- kernel 3: band chunks ci 0..1 (produces radW1 + smalls) --
__global__ void __launch_bounds__(512, 2)
main_bandA(const float* __restrict__ dist, const int* __restrict__ eis,
           const int* __restrict__ eit, float* __restrict__ out) {
    __shared__ float Bs[KB][132];
    __shared__ float Aw[16][KB][16];
    const int ci = blockIdx.x & 1;
    const int slice = blockIdx.x >> 1;
    band_run(ci, slice, ci >= 1, dist, eis, eit, out, Bs, Aw[threadIdx.x >> 5]);
}

// ---------------- kernel 4: mixed m-chunks (ci 2..5) + triplets ------------
__global__ void __launch_bounds__(512, 2)
k_mixed(const float* __restrict__ dist, const int* __restrict__ eis,
        const int* __restrict__ eit, const int* __restrict__ tin,
        const int* __restrict__ tout, const float* __restrict__ vec,
        float* __restrict__ out) {
    __shared__ float Bs[KB][132];
    __shared__ float Aw[16][KB][16];

    const int bx = blockIdx.x;
    if ((bx & 15) == 0) {
        // ---- m-chunk path: every 16th block ----
        const int mb = bx >> 4;            // 0..1043
        band_run(2 + (mb & 3), mb >> 2, true, dist, eis, eit, out,
                 Bs, Aw[threadIdx.x >> 5]);
        return;
    }

    // ---- triplet path ----
    const int tb = bx - ((bx + 15) >> 4);  // trip block id
    if (tb >= TRIP_BLKS) return;
    const int tid = threadIdx.x;
    const int gidx = tb * 512 + tid;
    const int tA = gidx >> 4;
    const int c = gidx & 15;
    if (tA >= T_N / 2) return;
    const int tB = tA + T_N / 2;
    const int lane = tid & 31;

    int ioA = 0, ioB = 0;
    float cosA = 0.f, cosB = 0.f;
    if ((lane & 15) == 0) {
        int iiA = tin[tA]; ioA = tout[tA];
        int iiB = tin[tB]; ioB = tout[tB];
        float3 a1 = *(const float3*)&vec[3 * (size_t)ioA];
        float3 b1 = *(const float3*)&vec[3 * (size_t)iiA];
        float3 a2 = *(const float3*)&vec[3 * (size_t)ioB];
        float3 b2 = *(const float3*)&vec[3 * (size_t)iiB];
        cosA = fminf(1.f, fmaxf(-1.f, a1.x * b1.x + a1.y * b1.y + a1.z * b1.z));
        cosB = fminf(1.f, fmaxf(-1.f, a2.x * b2.x + a2.y * b2.y + a2.z * b2.z));
    }
    const unsigned mask = 0xffffffffu;
    ioA  = __shfl_sync(mask, ioA, lane & 16, 32);
    cosA = __shfl_sync(mask, cosA, lane & 16, 32);
    ioB  = __shfl_sync(mask, ioB, lane & 16, 32);
    cosB = __shfl_sync(mask, cosB, lane & 16, 32);

    const float* rowA = g_radW1 + (size_t)ioA * 112 + c;
    const float* rowB = g_radW1 + (size_t)ioB * 112 + c;
    float rA[7], rB[7];
#pragma unroll
    for (int l = 0; l < 7; ++l) { rA[l] = rowA[16 * l]; rB[l] = rowB[16 * l]; }

    const float pf[7] = {0.28209479177387814f, 0.4886025119029199f,
                         0.6307831305050401f, 0.7463526651802308f,
                         0.8462843753216345f, 0.9356025796273889f,
                         1.0171072362820548f};
    float accA, accB;
    {
        float x = cosA;
        float P0 = 1.f, P1 = x;
        float P2 = (3.f * x * P1 - 1.f * P0) * (1.f / 2.f);
        float P3 = (5.f * x * P2 - 2.f * P1) * (1.f / 3.f);
        float P4 = (7.f * x * P3 - 3.f * P2) * (1.f / 4.f);
        float P5 = (9.f * x * P4 - 4.f * P3) * (1.f / 5.f);
        float P6 = (11.f * x * P5 - 5.f * P4) * (1.f / 6.f);
        accA = pf[0] * P0 * rA[0] + pf[1] * P1 * rA[1] + pf[2] * P2 * rA[2]
             + pf[3] * P3 * rA[3] + pf[4] * P4 * rA[4] + pf[5] * P5 * rA[5]
             + pf[6] * P6 * rA[6];
    }
    {
        float x = cosB;
        float P0 = 1.f, P1 = x;
        float P2 = (3.f * x * P1 - 1.f * P0) * (1.f / 2.f);
        float P3 = (5.f * x * P2 - 2.f * P1) * (1.f / 3.f);
        float P4 = (7.f * x * P3 - 3.f * P2) * (1.f / 4.f);
        float P5 = (9.f * x * P4 - 4.f * P3) * (1.f / 5.f);
        float P6 = (11.f * x * P5 - 5.f * P4) * (1.f / 6.f);
        accB = pf[0] * P0 * rB[0] + pf[1] * P1 * rB[1] + pf[2] * P2 * rB[2]
             + pf[3] * P3 * rB[3] + pf[4] * P4 * rB[4] + pf[5] * P5 * rB[5]
             + pf[6] * P6 * rB[6];
    }
    out[OFF_CIR + (size_t)tA * 16 + c] = accA;
    out[OFF_CIR + (size_t)tB * 16 + c] = accB;
}

// ---------------- launch ----------------
extern "C" void kernel_launch(void* const* d_in, const int* in_sizes, int n_in,
                              void* d_out, int out_size) {
    const float* h    = (const float*)d_in[0];
    const float* dist = (const float*)d_in[1];
    const float* vec  = (const float*)d_in[2];
    const int*   eis  = (const int*)d_in[3];
    const int*   eit  = (const int*)d_in[4];
    const int*   tin  = (const int*)d_in[5];
    const int*   tout = (const int*)d_in[6];
    const float* Wt   = (const float*)d_in[7];
    const float* Wc   = (const float*)d_in[8];
    const float* Wh   = (const float*)d_in[9];
    const float* Wo   = (const float*)d_in[10];
    const float* We   = (const float*)d_in[11];
    float* out = (float*)d_out;

    k_init<<<(128 * NCAT + 255) / 256, 256>>>(Wt, Wc, Wh, Wo, We);
    k_gemm_hist<<<GEMM_BLKS + HIST_BLKS, 256>>>(h, We, dist);
    k_scatter<<<(E_N + 1023) / 1024, 256>>>(dist);
    main_bandA<<<2 * NSL, 512>>>(dist, eis, eit, out);
    k_mixed<<<MIX_GRID, 512>>>(dist, eis, eit, tin, tout, vec, out);
}

// round 15
// speedup vs baseline: 1.1496x; 1.1496x over previous
#include <cuda_runtime.h>
#include <cstdint>
#include <math.h>

#define E_N      200000
#define A_NUM    8000
#define T_N      1000000
#define NCAT     672
#define EMB_EDGE 512
#define N_TILES  1563
#define NSL      521          // ceil(1563/3)
#define L_TILES  3

#define OFF_M    0ull
#define OFF_AT   102400000ull
#define OFF_OUT  105600000ull
#define OFF_RE2E 108800000ull
#define OFF_CIR  112000000ull

#define GEMM_BLKS 504
#define HIST_BLKS 128
#define KB 10      // band width (taps +/-4..5 kept; dropped taps < 4e-5)

__device__ float g_radW1[(size_t)E_N * 112];
__device__ float g_hW[2ull * A_NUM * EMB_EDGE];
__device__ float g_Wcat[128 * NCAT];            // [k][n]
__device__ int   g_cnt[128];
__device__ int   g_pos[128];
__device__ int   g_done;
__device__ int   g_order[N_TILES * 128];

// ---------------- helpers ----------------
__device__ __forceinline__ void ffma2(unsigned long long& d, unsigned long long a,
                                      unsigned long long b) {
    asm("fma.rn.f32x2 %0, %1, %2, %3;" : "=l"(d) : "l"(a), "l"(b), "l"(d));
}
__device__ __forceinline__ unsigned long long pack2(float x, float y) {
    unsigned long long r;
    asm("mov.b64 %0, {%1, %2};" : "=l"(r) : "f"(x), "f"(y));
    return r;
}
union F4U { float4 f; unsigned long long u[2]; };

__device__ __forceinline__ int edge_r0(float d) {
    float u = d * (127.0f / 12.0f);
    int r0 = __float2int_rn(u);
    return max(0, min(127, r0));
}

// ---------------- kernel 0: init + build wcat ----------------
__global__ void k_init(const float* __restrict__ Wt, const float* __restrict__ Wc,
                       const float* __restrict__ Wh, const float* __restrict__ Wo,
                       const float* __restrict__ We) {
    int i = blockIdx.x * blockDim.x + threadIdx.x;
    if (blockIdx.x == 0) {
        int tid = threadIdx.x;
        if (tid < 128) { g_cnt[tid] = 0; g_pos[tid] = 0; }
        if (tid == 128) g_done = 0;
        if (tid >= 129 && tid < 129 + (N_TILES * 128 - E_N))
            g_order[E_N + tid - 129] = -1;
    }
    if (i >= 128 * NCAT) return;
    int k = i / NCAT, n = i - k * NCAT;
    float v;
    if (n < 16)        v = Wt[k * 16 + n];
    else if (n < 32)   v = Wh[k * 16 + (n - 16)];
    else if (n < 48)   v = Wo[k * 16 + (n - 32)];
    else if (n < 160)  v = Wc[k * 112 + (n - 48)];
    else               v = We[(size_t)(512 + k) * EMB_EDGE + (n - 160)];
    g_Wcat[i] = v;
}

// ---------------- kernel 1: gemm_hw + histogram/scan ----------------
__global__ void __launch_bounds__(256, 2)
k_gemm_hist(const float* __restrict__ h, const float* __restrict__ We,
            const float* __restrict__ dist) {
    __shared__ float As[32][132];
    __shared__ float Bs[32][132];

    if (blockIdx.x >= GEMM_BLKS) {
        __shared__ int scnt[128];
        __shared__ int sv[128];
        __shared__ int sdone;
        const int hb = blockIdx.x - GEMM_BLKS;
        const int tid = threadIdx.x;
        if (tid < 128) scnt[tid] = 0;
        __syncthreads();
        for (int e = hb * 256 + tid; e < E_N; e += HIST_BLKS * 256)
            atomicAdd(&scnt[edge_r0(dist[e])], 1);
        __syncthreads();
        if (tid < 128 && scnt[tid] > 0) atomicAdd(&g_cnt[tid], scnt[tid]);
        __threadfence();
        if (tid == 0) {
            int o = atomicAdd(&g_done, 1);
            sdone = (o == HIST_BLKS - 1) ? 1 : 0;
        }
        __syncthreads();
        if (!sdone) return;
        int c0 = 0;
        if (tid < 128) { c0 = *((volatile int*)&g_cnt[tid]); sv[tid] = c0; }
        __syncthreads();
        for (int o = 1; o < 128; o <<= 1) {
            int v = 0;
            if (tid < 128 && tid >= o) v = sv[tid - o];
            __syncthreads();
            if (tid < 128) sv[tid] += v;
            __syncthreads();
        }
        if (tid < 128) g_pos[tid] = sv[tid] - c0;
        return;
    }

    const int bx = blockIdx.x;
    const int z = bx / 252;
    const int rem = bx % 252;
    const int by = rem / 4;
    const int bnx = rem % 4;
    const float* B = We + (size_t)z * 256 * EMB_EDGE;
    float* C = g_hW + (size_t)z * A_NUM * EMB_EDGE;
    const int m0 = by * 128;
    const int n0 = bnx * 128;
    const int tid = threadIdx.x;
    const int tx = tid & 15, ty = tid >> 4;

    unsigned long long acc[8][4];
#pragma unroll
    for (int i = 0; i < 8; ++i)
#pragma unroll
        for (int j = 0; j < 4; ++j) acc[i][j] = 0ull;

    for (int k0 = 0; k0 < 256; k0 += 32) {
        if (k0) __syncthreads();
#pragma unroll
        for (int i = tid; i < 128 * 32; i += 256) {
            int m = i >> 5, kk = i & 31;
            As[kk][m] = (m0 + m < A_NUM) ? h[(size_t)(m0 + m) * 256 + k0 + kk] : 0.f;
        }
#pragma unroll
        for (int i = tid * 4; i < 32 * 128; i += 1024) {
            int kk = i >> 7, n = i & 127;
            *(float4*)&Bs[kk][n] = *(const float4*)&B[(size_t)(k0 + kk) * EMB_EDGE + n0 + n];
        }
        __syncthreads();
#pragma unroll
        for (int kk = 0; kk < 32; ++kk) {
            float4 a0 = *(const float4*)&As[kk][ty * 8];
            float4 a1 = *(const float4*)&As[kk][ty * 8 + 4];
            F4U b0, b1;
            b0.f = *(const float4*)&Bs[kk][tx * 8];
            b1.f = *(const float4*)&Bs[kk][tx * 8 + 4];
            unsigned long long bb[4] = {b0.u[0], b0.u[1], b1.u[0], b1.u[1]};
            float av[8] = {a0.x, a0.y, a0.z, a0.w, a1.x, a1.y, a1.z, a1.w};
#pragma unroll
            for (int i = 0; i < 8; ++i) {
                unsigned long long a2 = pack2(av[i], av[i]);
#pragma unroll
                for (int j = 0; j < 4; ++j) ffma2(acc[i][j], a2, bb[j]);
            }
        }
    }
#pragma unroll
    for (int i = 0; i < 8; ++i) {
        int m = m0 + ty * 8 + i;
        if (m >= A_NUM) continue;
        float v[8];
#pragma unroll
        for (int j = 0; j < 4; ++j) {
            v[2 * j]     = __uint_as_float((unsigned)(acc[i][j] & 0xffffffffull));
            v[2 * j + 1] = __uint_as_float((unsigned)(acc[i][j] >> 32));
        }
        float* dst = C + (size_t)m * EMB_EDGE + n0 + tx * 8;
        *(float4*)dst       = make_float4(v[0], v[1], v[2], v[3]);
        *(float4*)(dst + 4) = make_float4(v[4], v[5], v[6], v[7]);
    }
}

// ---------------- kernel 2: scatter ----------------
__global__ void __launch_bounds__(256)
k_scatter(const float* __restrict__ dist) {
    __shared__ int scnt[128];
    __shared__ int sbase[128];
    const int tid = threadIdx.x;
    const int base = blockIdx.x * 1024;
    if (tid < 128) scnt[tid] = 0;
    __syncthreads();
    int r0[4], lp[4];
#pragma unroll
    for (int j = 0; j < 4; ++j) {
        int e = base + j * 256 + tid;
        r0[j] = -1;
        if (e < E_N) { r0[j] = edge_r0(dist[e]); lp[j] = atomicAdd(&scnt[r0[j]], 1); }
    }
    __syncthreads();
    if (tid < 128 && scnt[tid] > 0) sbase[tid] = atomicAdd(&g_pos[tid], scnt[tid]);
    __syncthreads();
#pragma unroll
    for (int j = 0; j < 4; ++j) {
        int e = base + j * 256 + tid;
        if (e < E_N) g_order[sbase[r0[j]] + lp[j]] = e;
    }
}

// ---------------- kernel 3: banded GEMM, warp-autonomous, KB=10 ------------
__global__ void __launch_bounds__(512, 2)
main_band(const float* __restrict__ dist, const int* __restrict__ eis,
          const int* __restrict__ eit, float* __restrict__ out) {
    __shared__ float Bs[KB][132];
    __shared__ float Aw[16][KB][16];   // per-warp A slabs

    const int ci = blockIdx.x % 6;
    const int slice = blockIdx.x / 6;
    const int n0 = ci * 128;
    const int tid = threadIdx.x;
    const int lane = tid & 31;
    const int warp = tid >> 5;
    const int warpRow = warp >> 1;            // 0..7  (16-row slab)
    const int warpCol = warp & 1;             // 0..1  (64-col slab)
    const int rblk = lane >> 3;               // 0..3
    const int cblk = lane & 7;                // 0..7
    const int c0 = warpCol * 64 + cblk * 4;   // quad0 col (quad1 at +32)
    const int el = lane & 15;                 // edge within slab
    const int dir = lane >> 4;                // 0: center+down, 1: up
    const int t0 = slice * L_TILES;
    const int t1 = min(t0 + L_TILES, N_TILES);
    const float E1 = 0.36787944117144233f;
    const bool needsHW = (ci >= 1);
    float (*myA)[16] = Aw[warp];

    // ---- prologue prefetch for t0 ----
    int e0p = t0 * 128;
    int id0N = g_order[e0p];
    int idN  = g_order[e0p + warpRow * 16 + el];
    float dist0N = dist[max(id0N, 0)];
    float distN  = dist[max(idN, 0)];
    int siN = 0, tiN = 0;
    if (needsHW) { int cidx = max(idN, 0); siN = eis[cidx]; tiN = eit[cidx]; }

    int kmin_prev = -1;
    for (int t = t0; t < t1; ++t) {
        const int e0 = t * 128;
        const float dist0 = dist0N, myd = distN;
        const int idp = idN, sip = siN, tip = tiN;
        const int kmin = max(0, edge_r0(dist0) - 4);

        // independent prefetch (g_order) for t+1
        const bool hasNext = (t + 1 < t1);
        if (hasNext) {
            const int e0n = (t + 1) * 128;
            id0N = g_order[e0n];
            idN  = g_order[e0n + warpRow * 16 + el];
        }

        // B refill when band moved (uniform; B zero-pads gk >= 128)
        if (kmin != kmin_prev) {
            __syncthreads();
            for (int i = tid; i < KB * 32; i += 512) {
                int k = i >> 5;
                int n = (i & 31) * 4;
                int gk = kmin + k, gn = n0 + n;
                float4 w = make_float4(0.f, 0.f, 0.f, 0.f);
                if (gk < 128 && gn < NCAT)
                    w = *(const float4*)&g_Wcat[gk * NCAT + gn];
                *(float4*)&Bs[k][n] = w;
            }
            __syncthreads();
            kmin_prev = kmin;
        }

        // A build: warp-private, 2 lanes per edge (dir split)
        {
            float f = 0.f, vc = 0.f;
            int r0v = kmin;
            if (idp >= 0) {
                float ds = myd * (1.0f / 12.0f);
                float ds2 = ds * ds, ds5 = ds2 * ds2 * ds;
                float env = (ds < 1.f) ? (1.f + ds5 * (-21.f + ds * (35.f - 15.f * ds))) : 0.f;
                float u = ds * 127.f;
                r0v = __float2int_rn(u);
                r0v = max(0, min(127, r0v));
                f = u - (float)r0v;
                vc = env * expf(-0.5f * f * f);
            }
            const int center = min(r0v - kmin, KB - 1);   // 4 or 5
            if (dir == 0) {
                float v = vc;
                myA[center][el] = v;
                float ratio = __expf(-f - 0.5f);
                for (int rel = center - 1; rel >= 0; --rel) {
                    v *= ratio; ratio *= E1;
                    myA[rel][el] = v;
                }
            } else {
                float ratio = __expf(f - 0.5f);
                float v = vc;
                for (int rel = center + 1; rel < KB; ++rel) {
                    v *= ratio; ratio *= E1;
                    myA[rel][el] = v;
                }
            }
        }
        __syncwarp();

        // dependent prefetch for t+1
        if (hasNext) {
            dist0N = dist[max(id0N, 0)];
            distN  = dist[max(idN, 0)];
            if (needsHW) { int cidx = max(idN, 0); siN = eis[cidx]; tiN = eit[cidx]; }
        }

        // 10-step k-loop, 4 rows x (4+4) cols per thread
        unsigned long long acc[4][4];
#pragma unroll
        for (int i = 0; i < 4; ++i)
#pragma unroll
            for (int j = 0; j < 4; ++j) acc[i][j] = 0ull;
#pragma unroll
        for (int kk = 0; kk < KB; ++kk) {
            float4 a = *(const float4*)&myA[kk][rblk * 4];
            F4U b0, b1;
            b0.f = *(const float4*)&Bs[kk][c0];
            b1.f = *(const float4*)&Bs[kk][c0 + 32];
            unsigned long long bb[4] = {b0.u[0], b0.u[1], b1.u[0], b1.u[1]};
            float av[4] = {a.x, a.y, a.z, a.w};
#pragma unroll
            for (int i = 0; i < 4; ++i) {
                unsigned long long a2 = pack2(av[i], av[i]);
#pragma unroll
                for (int j = 0; j < 4; ++j) ffma2(acc[i][j], a2, bb[j]);
            }
        }
        __syncwarp();   // all lanes done reading myA before next rebuild

        // epilogue: rows via warp shuffles (edge data lives in lanes 0..15)
        const int nbase = n0 + c0;
#pragma unroll
        for (int i = 0; i < 4; ++i) {
            const int src = rblk * 4 + i;
            const int id2 = __shfl_sync(0xffffffffu, idp, src, 32);
            const int si  = __shfl_sync(0xffffffffu, sip, src, 32);
            const int ti  = __shfl_sync(0xffffffffu, tip, src, 32);
            if (id2 < 0) continue;
            float v[8];
#pragma unroll
            for (int j = 0; j < 4; ++j) {
                v[2 * j]     = __uint_as_float((unsigned)(acc[i][j] & 0xffffffffull));
                v[2 * j + 1] = __uint_as_float((unsigned)(acc[i][j] >> 32));
            }
#pragma unroll
            for (int q = 0; q < 2; ++q) {
                const int nbq = nbase + q * 32;
                if (nbq >= NCAT) continue;
                const float* vq = v + q * 4;
                if (nbq >= 160) {
                    int j2 = nbq - 160;
                    const float* hw1 = g_hW + (size_t)si * EMB_EDGE + j2;
                    const float* hw2 = g_hW + (size_t)A_NUM * EMB_EDGE
                                       + (size_t)ti * EMB_EDGE + j2;
                    float4 a4 = *(const float4*)hw1;
                    float4 b4 = *(const float4*)hw2;
                    float x0 = vq[0] + a4.x + b4.x;
                    float x1 = vq[1] + a4.y + b4.y;
                    float x2 = vq[2] + a4.z + b4.z;
                    float x3 = vq[3] + a4.w + b4.w;
                    float4 o;
                    o.x = x0 * (1.0f / 0.6f) / (1.0f + __expf(-x0));
                    o.y = x1 * (1.0f / 0.6f) / (1.0f + __expf(-x1));
                    o.z = x2 * (1.0f / 0.6f) / (1.0f + __expf(-x2));
                    o.w = x3 * (1.0f / 0.6f) / (1.0f + __expf(-x3));
                    *(float4*)(out + OFF_M + (size_t)id2 * EMB_EDGE + j2) = o;
                } else if (nbq >= 48) {
                    *(float4*)(g_radW1 + (size_t)id2 * 112 + (nbq - 48)) =
                        make_float4(vq[0], vq[1], vq[2], vq[3]);
                } else {
                    int seg = nbq >> 4;
                    size_t base = (seg == 0) ? OFF_RE2E : (seg == 1) ? OFF_AT : OFF_OUT;
                    *(float4*)(out + base + (size_t)id2 * 16 + (nbq & 15)) =
                        make_float4(vq[0], vq[1], vq[2], vq[3]);
                }
            }
        }
    }
}

// ---------------- kernel 4: triplets, 2 per thread ----------
__global__ void __launch_bounds__(256)
trip_kernel(const int* __restrict__ tin, const int* __restrict__ tout,
            const float* __restrict__ vec, float* __restrict__ out) {
    const int gidx = blockIdx.x * blockDim.x + threadIdx.x;
    const int tA = gidx >> 4;
    const int c = gidx & 15;
    if (tA >= T_N / 2) return;
    const int tB = tA + T_N / 2;
    const int lane = threadIdx.x & 31;

    int ioA = 0, ioB = 0;
    float cosA = 0.f, cosB = 0.f;
    if ((lane & 15) == 0) {
        int iiA = tin[tA]; ioA = tout[tA];
        int iiB = tin[tB]; ioB = tout[tB];
        float3 a1 = *(const float3*)&vec[3 * (size_t)ioA];
        float3 b1 = *(const float3*)&vec[3 * (size_t)iiA];
        float3 a2 = *(const float3*)&vec[3 * (size_t)ioB];
        float3 b2 = *(const float3*)&vec[3 * (size_t)iiB];
        cosA = fminf(1.f, fmaxf(-1.f, a1.x * b1.x + a1.y * b1.y + a1.z * b1.z));
        cosB = fminf(1.f, fmaxf(-1.f, a2.x * b2.x + a2.y * b2.y + a2.z * b2.z));
    }
    const unsigned mask = 0xffffffffu;
    ioA  = __shfl_sync(mask, ioA, lane & 16, 32);
    cosA = __shfl_sync(mask, cosA, lane & 16, 32);
    ioB  = __shfl_sync(mask, ioB, lane & 16, 32);
    cosB = __shfl_sync(mask, cosB, lane & 16, 32);

    const float* rowA = g_radW1 + (size_t)ioA * 112 + c;
    const float* rowB = g_radW1 + (size_t)ioB * 112 + c;
    float rA[7], rB[7];
#pragma unroll
    for (int l = 0; l < 7; ++l) { rA[l] = rowA[16 * l]; rB[l] = rowB[16 * l]; }

    const float pf[7] = {0.28209479177387814f, 0.4886025119029199f,
                         0.6307831305050401f, 0.7463526651802308f,
                         0.8462843753216345f, 0.9356025796273889f,
                         1.0171072362820548f};
    float accA, accB;
    {
        float x = cosA;
        float P0 = 1.f, P1 = x;
        float P2 = (3.f * x * P1 - 1.f * P0) * (1.f / 2.f);
        float P3 = (5.f * x * P2 - 2.f * P1) * (1.f / 3.f);
        float P4 = (7.f * x * P3 - 3.f * P2) * (1.f / 4.f);
        float P5 = (9.f * x * P4 - 4.f * P3) * (1.f / 5.f);
        float P6 = (11.f * x * P5 - 5.f * P4) * (1.f / 6.f);
        accA = pf[0] * P0 * rA[0] + pf[1] * P1 * rA[1] + pf[2] * P2 * rA[2]
             + pf[3] * P3 * rA[3] + pf[4] * P4 * rA[4] + pf[5] * P5 * rA[5]
             + pf[6] * P6 * rA[6];
    }
    {
        float x = cosB;
        float P0 = 1.f, P1 = x;
        float P2 = (3.f * x * P1 - 1.f * P0) * (1.f / 2.f);
        float P3 = (5.f * x * P2 - 2.f * P1) * (1.f / 3.f);
        float P4 = (7.f * x * P3 - 3.f * P2) * (1.f / 4.f);
        float P5 = (9.f * x * P4 - 4.f * P3) * (1.f / 5.f);
        float P6 = (11.f * x * P5 - 5.f * P4) * (1.f / 6.f);
        accB = pf[0] * P0 * rB[0] + pf[1] * P1 * rB[1] + pf[2] * P2 * rB[2]
             + pf[3] * P3 * rB[3] + pf[4] * P4 * rB[4] + pf[5] * P5 * rB[5]
             + pf[6] * P6 * rB[6];
    }
    out[OFF_CIR + (size_t)tA * 16 + c] = accA;
    out[OFF_CIR + (size_t)tB * 16 + c] = accB;
}

// ---------------- launch ----------------
extern "C" void kernel_launch(void* const* d_in, const int* in_sizes, int n_in,
                              void* d_out, int out_size) {
    const float* h    = (const float*)d_in[0];
    const float* dist = (const float*)d_in[1];
    const float* vec  = (const float*)d_in[2];
    const int*   eis  = (const int*)d_in[3];
    const int*   eit  = (const int*)d_in[4];
    const int*   tin  = (const int*)d_in[5];
    const int*   tout = (const int*)d_in[6];
    const float* Wt   = (const float*)d_in[7];
    const float* Wc   = (const float*)d_in[8];
    const float* Wh   = (const float*)d_in[9];
    const float* Wo   = (const float*)d_in[10];
    const float* We   = (const float*)d_in[11];
    float* out = (float*)d_out;

    k_init<<<(128 * NCAT + 255) / 256, 256>>>(Wt, Wc, Wh, Wo, We);
    k_gemm_hist<<<GEMM_BLKS + HIST_BLKS, 256>>>(h, We, dist);
    k_scatter<<<(E_N + 1023) / 1024, 256>>>(dist);
    main_band<<<6 * NSL, 512>>>(dist, eis, eit, out);
    trip_kernel<<<(T_N / 2 * 16) / 256, 256>>>(tin, tout, vec, out);
}